// round 9
// baseline (speedup 1.0000x reference)
#include <cuda_runtime.h>
#include <cstdint>

// ---------------------------------------------------------------------------
// RobertaSelfAttention  B=2, N=2048, HID=1024, NH=16, HD=64
// Plan: tf32 mma.sync (m16n8k8) everywhere, fp32 accumulate.
//   K1: fused QKV projection (X @ W^T + b) -> scratch [b,h,n,d]
//   K2: flash attention per (b,h) with online softmax
// All tf32 operands pass through cvt.rna (round-to-nearest) to avoid the
// biased truncation error of raw f32 bit patterns.
// ---------------------------------------------------------------------------

#define DEVFN __device__ __forceinline__

constexpr int B_  = 2;
constexpr int N_  = 2048;
constexpr int HID_ = 1024;
constexpr int NH_ = 16;
constexpr int HD_ = 64;

// Scratch (static device globals: allocation-free)
__device__ float g_Q[B_ * NH_ * N_ * HD_];
__device__ float g_K[B_ * NH_ * N_ * HD_];
__device__ float g_V[B_ * NH_ * N_ * HD_];

DEVFN uint32_t f2tf(float x) {
    uint32_t u;
    asm("cvt.rna.tf32.f32 %0, %1;" : "=r"(u) : "f"(x));
    return u;
}
DEVFN float f2tff(float x) { return __uint_as_float(f2tf(x)); }

DEVFN void mma_tf32(float* d, const uint32_t* a, const uint32_t* b) {
    asm("mma.sync.aligned.m16n8k8.row.col.f32.tf32.tf32.f32 "
        "{%0,%1,%2,%3}, {%4,%5,%6,%7}, {%8,%9}, {%0,%1,%2,%3};"
        : "+f"(d[0]), "+f"(d[1]), "+f"(d[2]), "+f"(d[3])
        : "r"(a[0]), "r"(a[1]), "r"(a[2]), "r"(a[3]),
          "r"(b[0]), "r"(b[1]));
}

// ===========================================================================
// Kernel 1: QKV projection GEMM.  out[m,o] = sum_k X[m,k] * W[o,k] + b[o]
// BM=128 BN=128 BK=32, 256 threads (8 warps, 4x2), warp tile 32x64.
// Double-buffered smem, register-staged global loads, tf32 rounding at STS.
// blockIdx.z in {0,1,2} selects (Wq,bq,g_Q) / (Wk,bk,g_K) / (Wv,bv,g_V).
// Writes scratch in [b][h][n][d] layout.
// ===========================================================================
constexpr int BM = 128, BN = 128, BK = 32;
constexpr int AST = BK + 4;  // 36: stride ≡ 4 (mod 32) -> conflict-free frags
constexpr int QKV_SMEM = (2 * BM * AST + 2 * BN * AST) * 4;  // 73728 B

__global__ void __launch_bounds__(256, 1)
qkv_kernel(const float* __restrict__ X,
           const float* __restrict__ Wq, const float* __restrict__ bq,
           const float* __restrict__ Wk, const float* __restrict__ bk,
           const float* __restrict__ Wv, const float* __restrict__ bv) {
    extern __shared__ float sm[];
    float* As = sm;                  // [2][BM][AST]
    float* Bs = sm + 2 * BM * AST;   // [2][BN][AST]

    const int z = blockIdx.z;
    const float* W    = (z == 0) ? Wq : (z == 1) ? Wk : Wv;
    const float* bias = (z == 0) ? bq : (z == 1) ? bk : bv;
    float* dst        = (z == 0) ? g_Q : (z == 1) ? g_K : g_V;

    const int m0 = blockIdx.x * BM;
    const int o0 = blockIdx.y * BN;
    const int tid = threadIdx.x;
    const int lane = tid & 31;
    const int w = tid >> 5;
    const int wm = w & 3;   // 4 warps along M
    const int wn = w >> 2;  // 2 warps along N

    // staging: 128 rows x 8 float4 per row; thread covers rows srow+32i
    const int srow = tid >> 3;
    const int scol = (tid & 7) * 4;
    const float* Xp = X + (size_t)(m0 + srow) * HID_ + scol;
    const float* Wp = W + (size_t)(o0 + srow) * HID_ + scol;

    float4 ar[4], br[4];
    auto ldg = [&](int kt) {
#pragma unroll
        for (int i = 0; i < 4; i++) {
            ar[i] = *reinterpret_cast<const float4*>(Xp + kt * BK + (size_t)i * 32 * HID_);
            br[i] = *reinterpret_cast<const float4*>(Wp + kt * BK + (size_t)i * 32 * HID_);
        }
    };
    auto sts = [&](int buf) {
#pragma unroll
        for (int i = 0; i < 4; i++) {
            float* pa = As + buf * BM * AST + (srow + i * 32) * AST + scol;
            pa[0] = f2tff(ar[i].x); pa[1] = f2tff(ar[i].y);
            pa[2] = f2tff(ar[i].z); pa[3] = f2tff(ar[i].w);
            float* pb = Bs + buf * BN * AST + (srow + i * 32) * AST + scol;
            pb[0] = f2tff(br[i].x); pb[1] = f2tff(br[i].y);
            pb[2] = f2tff(br[i].z); pb[3] = f2tff(br[i].w);
        }
    };

    float acc[2][8][4];
#pragma unroll
    for (int mi = 0; mi < 2; mi++)
#pragma unroll
        for (int ni = 0; ni < 8; ni++)
#pragma unroll
            for (int r = 0; r < 4; r++) acc[mi][ni][r] = 0.f;

    ldg(0);
    sts(0);
    __syncthreads();

    const int KT = HID_ / BK;  // 32
    for (int kt = 0; kt < KT; kt++) {
        const int cur = kt & 1;
        if (kt + 1 < KT) ldg(kt + 1);

        const float* Ab = As + cur * BM * AST + (wm * 32) * AST;
        const float* Bb = Bs + cur * BN * AST + (wn * 64) * AST;
#pragma unroll
        for (int ks = 0; ks < 4; ks++) {
            uint32_t a[2][4];
#pragma unroll
            for (int mi = 0; mi < 2; mi++) {
                const float* ap = Ab + mi * 16 * AST + ks * 8;
                a[mi][0] = __float_as_uint(ap[(lane >> 2) * AST + (lane & 3)]);
                a[mi][1] = __float_as_uint(ap[((lane >> 2) + 8) * AST + (lane & 3)]);
                a[mi][2] = __float_as_uint(ap[(lane >> 2) * AST + (lane & 3) + 4]);
                a[mi][3] = __float_as_uint(ap[((lane >> 2) + 8) * AST + (lane & 3) + 4]);
            }
#pragma unroll
            for (int ni = 0; ni < 8; ni++) {
                const float* bp = Bb + ni * 8 * AST + ks * 8;
                uint32_t b2[2];
                b2[0] = __float_as_uint(bp[(lane >> 2) * AST + (lane & 3)]);
                b2[1] = __float_as_uint(bp[(lane >> 2) * AST + (lane & 3) + 4]);
                mma_tf32(acc[0][ni], a[0], b2);
                mma_tf32(acc[1][ni], a[1], b2);
            }
        }
        if (kt + 1 < KT) sts((kt + 1) & 1);
        __syncthreads();
    }

    // Epilogue: add bias, scatter to [b][h][n][d]
#pragma unroll
    for (int mi = 0; mi < 2; mi++) {
        const int row = m0 + wm * 32 + mi * 16 + (lane >> 2);
        const int bb = row >> 11;       // / N_
        const int nn = row & (N_ - 1);
#pragma unroll
        for (int ni = 0; ni < 8; ni++) {
            const int col = o0 + wn * 64 + ni * 8 + 2 * (lane & 3);
            const int hh = col >> 6;
            const int dd = col & 63;
            const float b0v = bias[col];
            const float b1v = bias[col + 1];
            float* p0 = dst + (((size_t)(bb * NH_ + hh) * N_ + nn) * HD_ + dd);
            float* p1 = dst + (((size_t)(bb * NH_ + hh) * N_ + nn + 8) * HD_ + dd);
            float2 v0 = make_float2(acc[mi][ni][0] + b0v, acc[mi][ni][1] + b1v);
            float2 v1 = make_float2(acc[mi][ni][2] + b0v, acc[mi][ni][3] + b1v);
            *reinterpret_cast<float2*>(p0) = v0;
            *reinterpret_cast<float2*>(p1) = v1;
        }
    }
}

// ===========================================================================
// Kernel 2: flash attention.  grid (N/128, NH, B), 256 threads (8 warps).
// Each warp owns 16 query rows. Q fragments live in registers (scale folded).
// K/V tiles (128x64) double-buffered in smem with LDG->cvt->STS staging.
// P staged through smem (tf32) for the PV mma.
// Smem strides: Ks 68 (≡4 mod 32), Vs 72 (≡8), Ps 132 (≡4) -> fragment LDS
// patterns are bank-conflict-free.
// ===========================================================================
constexpr int KST = 68, VST = 72, PST = 132;
constexpr int ATTN_SMEM =
    (2 * 128 * KST + 2 * 128 * VST + 128 * PST + N_) * 4;  // 219136 B

__global__ void __launch_bounds__(256, 1)
attn_kernel(const float* __restrict__ mask, float* __restrict__ out) {
    extern __shared__ float sm[];
    float* Ks = sm;                      // [2][128][KST]
    float* Vs = Ks + 2 * 128 * KST;      // [2][128][VST]
    float* Ps = Vs + 2 * 128 * VST;      // [128][PST]
    float* Ms = Ps + 128 * PST;          // [N_]

    const int b = blockIdx.z;
    const int h = blockIdx.y;
    const int q0 = blockIdx.x * 128;
    const int tid = threadIdx.x;
    const int lane = tid & 31;
    const int w = tid >> 5;

    const size_t hb = (size_t)(b * NH_ + h) * N_ * HD_;
    const float* Qb = g_Q + hb + (size_t)q0 * HD_;
    const float* Kb = g_K + hb;
    const float* Vb = g_V + hb;

    // whole-sequence mask for this batch into smem (8 KB)
    {
        const float4* mp = reinterpret_cast<const float4*>(mask + (size_t)b * N_);
        float4* ms = reinterpret_cast<float4*>(Ms);
#pragma unroll
        for (int i = 0; i < 2; i++) ms[tid + 256 * i] = mp[tid + 256 * i];
    }

    // Q fragments in registers (scale 1/8 folded in, tf32-rounded)
    uint32_t qf[8][4];
    {
        const float* qp = Qb + (size_t)(w * 16 + (lane >> 2)) * HD_;
#pragma unroll
        for (int ks = 0; ks < 8; ks++) {
            qf[ks][0] = f2tf(qp[ks * 8 + (lane & 3)] * 0.125f);
            qf[ks][1] = f2tf(qp[8 * HD_ + ks * 8 + (lane & 3)] * 0.125f);
            qf[ks][2] = f2tf(qp[ks * 8 + (lane & 3) + 4] * 0.125f);
            qf[ks][3] = f2tf(qp[8 * HD_ + ks * 8 + (lane & 3) + 4] * 0.125f);
        }
    }

    // tile staging: 128 rows x 16 float4 per row
    const int srow = tid >> 4;
    const int scol = (tid & 15) * 4;
    float4 stg[8];
    auto ldgT = [&](const float* base, int kt) {
        const float* p = base + (size_t)(kt * 128 + srow) * HD_ + scol;
#pragma unroll
        for (int i = 0; i < 8; i++)
            stg[i] = *reinterpret_cast<const float4*>(p + (size_t)i * 16 * HD_);
    };
    auto stsT = [&](float* dstS, int stride) {
#pragma unroll
        for (int i = 0; i < 8; i++) {
            float* p = dstS + (srow + i * 16) * stride + scol;
            p[0] = f2tff(stg[i].x); p[1] = f2tff(stg[i].y);
            p[2] = f2tff(stg[i].z); p[3] = f2tff(stg[i].w);
        }
    };

    ldgT(Kb, 0); stsT(Ks, KST);
    ldgT(Vb, 0); stsT(Vs, VST);
    __syncthreads();

    float o[8][4];
#pragma unroll
    for (int ni = 0; ni < 8; ni++)
#pragma unroll
        for (int r = 0; r < 4; r++) o[ni][r] = 0.f;
    float m0r = -INFINITY, m1r = -INFINITY, l0 = 0.f, l1 = 0.f;

    const int NKT = N_ / 128;  // 16
    for (int kt = 0; kt < NKT; kt++) {
        const int cur = kt & 1;
        const float* Kc = Ks + cur * 128 * KST;
        const float* Vc = Vs + cur * 128 * VST;

        if (kt + 1 < NKT) ldgT(Kb, kt + 1);  // prefetch K(kt+1) into regs

        // ---- S = Q K^T (pre-scaled) ----
        float s[16][4];
#pragma unroll
        for (int ni = 0; ni < 16; ni++)
#pragma unroll
            for (int r = 0; r < 4; r++) s[ni][r] = 0.f;

#pragma unroll
        for (int ks = 0; ks < 8; ks++) {
#pragma unroll
            for (int ni = 0; ni < 16; ni++) {
                const float* bp = Kc + (ni * 8 + (lane >> 2)) * KST + ks * 8 + (lane & 3);
                uint32_t b2[2] = { __float_as_uint(bp[0]), __float_as_uint(bp[4]) };
                mma_tf32(s[ni], qf[ks], b2);
            }
        }

        // ---- online softmax ----
        float mx0 = -INFINITY, mx1 = -INFINITY;
#pragma unroll
        for (int ni = 0; ni < 16; ni++) {
            const float2 mk = *reinterpret_cast<const float2*>(
                Ms + kt * 128 + ni * 8 + 2 * (lane & 3));
            s[ni][0] += mk.x; s[ni][1] += mk.y;
            s[ni][2] += mk.x; s[ni][3] += mk.y;
            mx0 = fmaxf(mx0, fmaxf(s[ni][0], s[ni][1]));
            mx1 = fmaxf(mx1, fmaxf(s[ni][2], s[ni][3]));
        }
        mx0 = fmaxf(mx0, __shfl_xor_sync(0xffffffffu, mx0, 1));
        mx0 = fmaxf(mx0, __shfl_xor_sync(0xffffffffu, mx0, 2));
        mx1 = fmaxf(mx1, __shfl_xor_sync(0xffffffffu, mx1, 1));
        mx1 = fmaxf(mx1, __shfl_xor_sync(0xffffffffu, mx1, 2));

        const float mn0 = fmaxf(m0r, mx0);
        const float mn1 = fmaxf(m1r, mx1);
        const float a0 = __expf(m0r - mn0);
        const float a1 = __expf(m1r - mn1);
        m0r = mn0; m1r = mn1;

        float rs0 = 0.f, rs1 = 0.f;
#pragma unroll
        for (int ni = 0; ni < 16; ni++) {
            s[ni][0] = __expf(s[ni][0] - mn0);
            s[ni][1] = __expf(s[ni][1] - mn0);
            s[ni][2] = __expf(s[ni][2] - mn1);
            s[ni][3] = __expf(s[ni][3] - mn1);
            rs0 += s[ni][0] + s[ni][1];
            rs1 += s[ni][2] + s[ni][3];
        }
        rs0 += __shfl_xor_sync(0xffffffffu, rs0, 1);
        rs0 += __shfl_xor_sync(0xffffffffu, rs0, 2);
        rs1 += __shfl_xor_sync(0xffffffffu, rs1, 1);
        rs1 += __shfl_xor_sync(0xffffffffu, rs1, 2);
        l0 = l0 * a0 + rs0;
        l1 = l1 * a1 + rs1;

        // ---- write P (tf32) to smem ----
        {
            float* pr = Ps + (w * 16 + (lane >> 2)) * PST + 2 * (lane & 3);
#pragma unroll
            for (int ni = 0; ni < 16; ni++) {
                *reinterpret_cast<float2*>(pr + ni * 8) =
                    make_float2(f2tff(s[ni][0]), f2tff(s[ni][1]));
                *reinterpret_cast<float2*>(pr + 8 * PST + ni * 8) =
                    make_float2(f2tff(s[ni][2]), f2tff(s[ni][3]));
            }
        }
        __syncthreads();  // Ps visible; alt K buffer fully consumed (kt-1)

        if (kt + 1 < NKT) {
            stsT(Ks + (cur ^ 1) * 128 * KST, KST);  // commit staged K
            ldgT(Vb, kt + 1);                       // prefetch V(kt+1)
        }

        // ---- O = O*alpha + P V ----
#pragma unroll
        for (int ni = 0; ni < 8; ni++) {
            o[ni][0] *= a0; o[ni][1] *= a0;
            o[ni][2] *= a1; o[ni][3] *= a1;
        }
#pragma unroll
        for (int ks = 0; ks < 16; ks++) {
            const float* pp = Ps + (w * 16) * PST + ks * 8;
            uint32_t a4[4];
            a4[0] = __float_as_uint(pp[(lane >> 2) * PST + (lane & 3)]);
            a4[1] = __float_as_uint(pp[((lane >> 2) + 8) * PST + (lane & 3)]);
            a4[2] = __float_as_uint(pp[(lane >> 2) * PST + (lane & 3) + 4]);
            a4[3] = __float_as_uint(pp[((lane >> 2) + 8) * PST + (lane & 3) + 4]);
#pragma unroll
            for (int ni = 0; ni < 8; ni++) {
                const float* vp = Vc + (ks * 8 + (lane & 3)) * VST + ni * 8 + (lane >> 2);
                uint32_t b2[2] = { __float_as_uint(vp[0]),
                                   __float_as_uint(vp[4 * VST]) };
                mma_tf32(o[ni], a4, b2);
            }
        }

        if (kt + 1 < NKT) stsT(Vs + (cur ^ 1) * 128 * VST, VST);
        __syncthreads();
    }

    // ---- epilogue: O / l -> out[b][n][h*HD + d] ----
    const float inv0 = 1.f / l0;
    const float inv1 = 1.f / l1;
    const int n0 = q0 + w * 16 + (lane >> 2);
    float* op = out + ((size_t)b * N_ + n0) * HID_ + h * HD_ + 2 * (lane & 3);
#pragma unroll
    for (int ni = 0; ni < 8; ni++) {
        *reinterpret_cast<float2*>(op + ni * 8) =
            make_float2(o[ni][0] * inv0, o[ni][1] * inv0);
        *reinterpret_cast<float2*>(op + (size_t)8 * HID_ + ni * 8) =
            make_float2(o[ni][2] * inv1, o[ni][3] * inv1);
    }
}

// ===========================================================================
extern "C" void kernel_launch(void* const* d_in, const int* in_sizes, int n_in,
                              void* d_out, int out_size) {
    const float* X    = (const float*)d_in[0];
    const float* mask = (const float*)d_in[1];
    const float* Wq   = (const float*)d_in[2];
    const float* bq   = (const float*)d_in[3];
    const float* Wk   = (const float*)d_in[4];
    const float* bk   = (const float*)d_in[5];
    const float* Wv   = (const float*)d_in[6];
    const float* bv   = (const float*)d_in[7];
    float* out = (float*)d_out;

    cudaFuncSetAttribute(qkv_kernel,
                         cudaFuncAttributeMaxDynamicSharedMemorySize, QKV_SMEM);
    cudaFuncSetAttribute(attn_kernel,
                         cudaFuncAttributeMaxDynamicSharedMemorySize, ATTN_SMEM);

    // QKV: M=4096 -> 32 blocks, O=1024 -> 8 blocks, z selects Q/K/V
    qkv_kernel<<<dim3(32, 8, 3), 256, QKV_SMEM>>>(X, Wq, bq, Wk, bk, Wv, bv);
    // Attention: (q-tile, head, batch)
    attn_kernel<<<dim3(N_ / 128, NH_, B_), 256, ATTN_SMEM>>>(mask, out);
}

// round 12
// speedup vs baseline: 1.0006x; 1.0006x over previous
#include <cuda_runtime.h>
#include <cstdint>

// ---------------------------------------------------------------------------
// RobertaSelfAttention  B=2, N=2048, HID=1024, NH=16, HD=64
// Plan: tf32 mma.sync (m16n8k8) everywhere, fp32 accumulate.
//   K1: fused QKV projection (X @ W^T + b) -> scratch [b,h,n,d]
//   K2: flash attention per (b,h) with online softmax
// All tf32 operands pass through cvt.rna (round-to-nearest) to avoid the
// biased truncation error of raw f32 bit patterns.
// ---------------------------------------------------------------------------

#define DEVFN __device__ __forceinline__

constexpr int B_  = 2;
constexpr int N_  = 2048;
constexpr int HID_ = 1024;
constexpr int NH_ = 16;
constexpr int HD_ = 64;

// Scratch (static device globals: allocation-free)
__device__ float g_Q[B_ * NH_ * N_ * HD_];
__device__ float g_K[B_ * NH_ * N_ * HD_];
__device__ float g_V[B_ * NH_ * N_ * HD_];

DEVFN uint32_t f2tf(float x) {
    uint32_t u;
    asm("cvt.rna.tf32.f32 %0, %1;" : "=r"(u) : "f"(x));
    return u;
}
DEVFN float f2tff(float x) { return __uint_as_float(f2tf(x)); }

DEVFN void mma_tf32(float* d, const uint32_t* a, const uint32_t* b) {
    asm("mma.sync.aligned.m16n8k8.row.col.f32.tf32.tf32.f32 "
        "{%0,%1,%2,%3}, {%4,%5,%6,%7}, {%8,%9}, {%0,%1,%2,%3};"
        : "+f"(d[0]), "+f"(d[1]), "+f"(d[2]), "+f"(d[3])
        : "r"(a[0]), "r"(a[1]), "r"(a[2]), "r"(a[3]),
          "r"(b[0]), "r"(b[1]));
}

// ===========================================================================
// Kernel 1: QKV projection GEMM.  out[m,o] = sum_k X[m,k] * W[o,k] + b[o]
// BM=128 BN=128 BK=32, 256 threads (8 warps, 4x2), warp tile 32x64.
// Double-buffered smem, register-staged global loads, tf32 rounding at STS.
// blockIdx.z in {0,1,2} selects (Wq,bq,g_Q) / (Wk,bk,g_K) / (Wv,bv,g_V).
// Writes scratch in [b][h][n][d] layout.
// ===========================================================================
constexpr int BM = 128, BN = 128, BK = 32;
constexpr int AST = BK + 4;  // 36: stride ≡ 4 (mod 32) -> conflict-free frags
constexpr int QKV_SMEM = (2 * BM * AST + 2 * BN * AST) * 4;  // 73728 B

__global__ void __launch_bounds__(256, 1)
qkv_kernel(const float* __restrict__ X,
           const float* __restrict__ Wq, const float* __restrict__ bq,
           const float* __restrict__ Wk, const float* __restrict__ bk,
           const float* __restrict__ Wv, const float* __restrict__ bv) {
    extern __shared__ float sm[];
    float* As = sm;                  // [2][BM][AST]
    float* Bs = sm + 2 * BM * AST;   // [2][BN][AST]

    const int z = blockIdx.z;
    const float* W    = (z == 0) ? Wq : (z == 1) ? Wk : Wv;
    const float* bias = (z == 0) ? bq : (z == 1) ? bk : bv;
    float* dst        = (z == 0) ? g_Q : (z == 1) ? g_K : g_V;

    const int m0 = blockIdx.x * BM;
    const int o0 = blockIdx.y * BN;
    const int tid = threadIdx.x;
    const int lane = tid & 31;
    const int w = tid >> 5;
    const int wm = w & 3;   // 4 warps along M
    const int wn = w >> 2;  // 2 warps along N

    // staging: 128 rows x 8 float4 per row; thread covers rows srow+32i
    const int srow = tid >> 3;
    const int scol = (tid & 7) * 4;
    const float* Xp = X + (size_t)(m0 + srow) * HID_ + scol;
    const float* Wp = W + (size_t)(o0 + srow) * HID_ + scol;

    float4 ar[4], br[4];
    auto ldg = [&](int kt) {
#pragma unroll
        for (int i = 0; i < 4; i++) {
            ar[i] = *reinterpret_cast<const float4*>(Xp + kt * BK + (size_t)i * 32 * HID_);
            br[i] = *reinterpret_cast<const float4*>(Wp + kt * BK + (size_t)i * 32 * HID_);
        }
    };
    auto sts = [&](int buf) {
#pragma unroll
        for (int i = 0; i < 4; i++) {
            float* pa = As + buf * BM * AST + (srow + i * 32) * AST + scol;
            pa[0] = f2tff(ar[i].x); pa[1] = f2tff(ar[i].y);
            pa[2] = f2tff(ar[i].z); pa[3] = f2tff(ar[i].w);
            float* pb = Bs + buf * BN * AST + (srow + i * 32) * AST + scol;
            pb[0] = f2tff(br[i].x); pb[1] = f2tff(br[i].y);
            pb[2] = f2tff(br[i].z); pb[3] = f2tff(br[i].w);
        }
    };

    float acc[2][8][4];
#pragma unroll
    for (int mi = 0; mi < 2; mi++)
#pragma unroll
        for (int ni = 0; ni < 8; ni++)
#pragma unroll
            for (int r = 0; r < 4; r++) acc[mi][ni][r] = 0.f;

    ldg(0);
    sts(0);
    __syncthreads();

    const int KT = HID_ / BK;  // 32
    for (int kt = 0; kt < KT; kt++) {
        const int cur = kt & 1;
        if (kt + 1 < KT) ldg(kt + 1);

        const float* Ab = As + cur * BM * AST + (wm * 32) * AST;
        const float* Bb = Bs + cur * BN * AST + (wn * 64) * AST;
#pragma unroll
        for (int ks = 0; ks < 4; ks++) {
            uint32_t a[2][4];
#pragma unroll
            for (int mi = 0; mi < 2; mi++) {
                const float* ap = Ab + mi * 16 * AST + ks * 8;
                a[mi][0] = __float_as_uint(ap[(lane >> 2) * AST + (lane & 3)]);
                a[mi][1] = __float_as_uint(ap[((lane >> 2) + 8) * AST + (lane & 3)]);
                a[mi][2] = __float_as_uint(ap[(lane >> 2) * AST + (lane & 3) + 4]);
                a[mi][3] = __float_as_uint(ap[((lane >> 2) + 8) * AST + (lane & 3) + 4]);
            }
#pragma unroll
            for (int ni = 0; ni < 8; ni++) {
                const float* bp = Bb + ni * 8 * AST + ks * 8;
                uint32_t b2[2];
                b2[0] = __float_as_uint(bp[(lane >> 2) * AST + (lane & 3)]);
                b2[1] = __float_as_uint(bp[(lane >> 2) * AST + (lane & 3) + 4]);
                mma_tf32(acc[0][ni], a[0], b2);
                mma_tf32(acc[1][ni], a[1], b2);
            }
        }
        if (kt + 1 < KT) sts((kt + 1) & 1);
        __syncthreads();
    }

    // Epilogue: add bias, scatter to [b][h][n][d]
#pragma unroll
    for (int mi = 0; mi < 2; mi++) {
        const int row = m0 + wm * 32 + mi * 16 + (lane >> 2);
        const int bb = row >> 11;       // / N_
        const int nn = row & (N_ - 1);
#pragma unroll
        for (int ni = 0; ni < 8; ni++) {
            const int col = o0 + wn * 64 + ni * 8 + 2 * (lane & 3);
            const int hh = col >> 6;
            const int dd = col & 63;
            const float b0v = bias[col];
            const float b1v = bias[col + 1];
            float* p0 = dst + (((size_t)(bb * NH_ + hh) * N_ + nn) * HD_ + dd);
            float* p1 = dst + (((size_t)(bb * NH_ + hh) * N_ + nn + 8) * HD_ + dd);
            float2 v0 = make_float2(acc[mi][ni][0] + b0v, acc[mi][ni][1] + b1v);
            float2 v1 = make_float2(acc[mi][ni][2] + b0v, acc[mi][ni][3] + b1v);
            *reinterpret_cast<float2*>(p0) = v0;
            *reinterpret_cast<float2*>(p1) = v1;
        }
    }
}

// ===========================================================================
// Kernel 2: flash attention.  grid (N/128, NH, B), 256 threads (8 warps).
// Each warp owns 16 query rows. Q fragments live in registers (scale folded).
// K/V tiles (128x64) double-buffered in smem with LDG->cvt->STS staging.
// P staged through smem (tf32) for the PV mma.
// Smem strides: Ks 68 (≡4 mod 32), Vs 72 (≡8), Ps 132 (≡4) -> fragment LDS
// patterns are bank-conflict-free.
// ===========================================================================
constexpr int KST = 68, VST = 72, PST = 132;
constexpr int ATTN_SMEM =
    (2 * 128 * KST + 2 * 128 * VST + 128 * PST + N_) * 4;  // 219136 B

__global__ void __launch_bounds__(256, 1)
attn_kernel(const float* __restrict__ mask, float* __restrict__ out) {
    extern __shared__ float sm[];
    float* Ks = sm;                      // [2][128][KST]
    float* Vs = Ks + 2 * 128 * KST;      // [2][128][VST]
    float* Ps = Vs + 2 * 128 * VST;      // [128][PST]
    float* Ms = Ps + 128 * PST;          // [N_]

    const int b = blockIdx.z;
    const int h = blockIdx.y;
    const int q0 = blockIdx.x * 128;
    const int tid = threadIdx.x;
    const int lane = tid & 31;
    const int w = tid >> 5;

    const size_t hb = (size_t)(b * NH_ + h) * N_ * HD_;
    const float* Qb = g_Q + hb + (size_t)q0 * HD_;
    const float* Kb = g_K + hb;
    const float* Vb = g_V + hb;

    // whole-sequence mask for this batch into smem (8 KB)
    {
        const float4* mp = reinterpret_cast<const float4*>(mask + (size_t)b * N_);
        float4* ms = reinterpret_cast<float4*>(Ms);
#pragma unroll
        for (int i = 0; i < 2; i++) ms[tid + 256 * i] = mp[tid + 256 * i];
    }

    // Q fragments in registers (scale 1/8 folded in, tf32-rounded)
    uint32_t qf[8][4];
    {
        const float* qp = Qb + (size_t)(w * 16 + (lane >> 2)) * HD_;
#pragma unroll
        for (int ks = 0; ks < 8; ks++) {
            qf[ks][0] = f2tf(qp[ks * 8 + (lane & 3)] * 0.125f);
            qf[ks][1] = f2tf(qp[8 * HD_ + ks * 8 + (lane & 3)] * 0.125f);
            qf[ks][2] = f2tf(qp[ks * 8 + (lane & 3) + 4] * 0.125f);
            qf[ks][3] = f2tf(qp[8 * HD_ + ks * 8 + (lane & 3) + 4] * 0.125f);
        }
    }

    // tile staging: 128 rows x 16 float4 per row
    const int srow = tid >> 4;
    const int scol = (tid & 15) * 4;
    float4 stg[8];
    auto ldgT = [&](const float* base, int kt) {
        const float* p = base + (size_t)(kt * 128 + srow) * HD_ + scol;
#pragma unroll
        for (int i = 0; i < 8; i++)
            stg[i] = *reinterpret_cast<const float4*>(p + (size_t)i * 16 * HD_);
    };
    auto stsT = [&](float* dstS, int stride) {
#pragma unroll
        for (int i = 0; i < 8; i++) {
            float* p = dstS + (srow + i * 16) * stride + scol;
            p[0] = f2tff(stg[i].x); p[1] = f2tff(stg[i].y);
            p[2] = f2tff(stg[i].z); p[3] = f2tff(stg[i].w);
        }
    };

    ldgT(Kb, 0); stsT(Ks, KST);
    ldgT(Vb, 0); stsT(Vs, VST);
    __syncthreads();

    float o[8][4];
#pragma unroll
    for (int ni = 0; ni < 8; ni++)
#pragma unroll
        for (int r = 0; r < 4; r++) o[ni][r] = 0.f;
    float m0r = -INFINITY, m1r = -INFINITY, l0 = 0.f, l1 = 0.f;

    const int NKT = N_ / 128;  // 16
    for (int kt = 0; kt < NKT; kt++) {
        const int cur = kt & 1;
        const float* Kc = Ks + cur * 128 * KST;
        const float* Vc = Vs + cur * 128 * VST;

        if (kt + 1 < NKT) ldgT(Kb, kt + 1);  // prefetch K(kt+1) into regs

        // ---- S = Q K^T (pre-scaled) ----
        float s[16][4];
#pragma unroll
        for (int ni = 0; ni < 16; ni++)
#pragma unroll
            for (int r = 0; r < 4; r++) s[ni][r] = 0.f;

#pragma unroll
        for (int ks = 0; ks < 8; ks++) {
#pragma unroll
            for (int ni = 0; ni < 16; ni++) {
                const float* bp = Kc + (ni * 8 + (lane >> 2)) * KST + ks * 8 + (lane & 3);
                uint32_t b2[2] = { __float_as_uint(bp[0]), __float_as_uint(bp[4]) };
                mma_tf32(s[ni], qf[ks], b2);
            }
        }

        // ---- online softmax ----
        float mx0 = -INFINITY, mx1 = -INFINITY;
#pragma unroll
        for (int ni = 0; ni < 16; ni++) {
            const float2 mk = *reinterpret_cast<const float2*>(
                Ms + kt * 128 + ni * 8 + 2 * (lane & 3));
            s[ni][0] += mk.x; s[ni][1] += mk.y;
            s[ni][2] += mk.x; s[ni][3] += mk.y;
            mx0 = fmaxf(mx0, fmaxf(s[ni][0], s[ni][1]));
            mx1 = fmaxf(mx1, fmaxf(s[ni][2], s[ni][3]));
        }
        mx0 = fmaxf(mx0, __shfl_xor_sync(0xffffffffu, mx0, 1));
        mx0 = fmaxf(mx0, __shfl_xor_sync(0xffffffffu, mx0, 2));
        mx1 = fmaxf(mx1, __shfl_xor_sync(0xffffffffu, mx1, 1));
        mx1 = fmaxf(mx1, __shfl_xor_sync(0xffffffffu, mx1, 2));

        const float mn0 = fmaxf(m0r, mx0);
        const float mn1 = fmaxf(m1r, mx1);
        const float a0 = __expf(m0r - mn0);
        const float a1 = __expf(m1r - mn1);
        m0r = mn0; m1r = mn1;

        float rs0 = 0.f, rs1 = 0.f;
#pragma unroll
        for (int ni = 0; ni < 16; ni++) {
            s[ni][0] = __expf(s[ni][0] - mn0);
            s[ni][1] = __expf(s[ni][1] - mn0);
            s[ni][2] = __expf(s[ni][2] - mn1);
            s[ni][3] = __expf(s[ni][3] - mn1);
            rs0 += s[ni][0] + s[ni][1];
            rs1 += s[ni][2] + s[ni][3];
        }
        rs0 += __shfl_xor_sync(0xffffffffu, rs0, 1);
        rs0 += __shfl_xor_sync(0xffffffffu, rs0, 2);
        rs1 += __shfl_xor_sync(0xffffffffu, rs1, 1);
        rs1 += __shfl_xor_sync(0xffffffffu, rs1, 2);
        l0 = l0 * a0 + rs0;
        l1 = l1 * a1 + rs1;

        // ---- write P (tf32) to smem ----
        {
            float* pr = Ps + (w * 16 + (lane >> 2)) * PST + 2 * (lane & 3);
#pragma unroll
            for (int ni = 0; ni < 16; ni++) {
                *reinterpret_cast<float2*>(pr + ni * 8) =
                    make_float2(f2tff(s[ni][0]), f2tff(s[ni][1]));
                *reinterpret_cast<float2*>(pr + 8 * PST + ni * 8) =
                    make_float2(f2tff(s[ni][2]), f2tff(s[ni][3]));
            }
        }
        __syncthreads();  // Ps visible; alt K buffer fully consumed (kt-1)

        if (kt + 1 < NKT) {
            stsT(Ks + (cur ^ 1) * 128 * KST, KST);  // commit staged K
            ldgT(Vb, kt + 1);                       // prefetch V(kt+1)
        }

        // ---- O = O*alpha + P V ----
#pragma unroll
        for (int ni = 0; ni < 8; ni++) {
            o[ni][0] *= a0; o[ni][1] *= a0;
            o[ni][2] *= a1; o[ni][3] *= a1;
        }
#pragma unroll
        for (int ks = 0; ks < 16; ks++) {
            const float* pp = Ps + (w * 16) * PST + ks * 8;
            uint32_t a4[4];
            a4[0] = __float_as_uint(pp[(lane >> 2) * PST + (lane & 3)]);
            a4[1] = __float_as_uint(pp[((lane >> 2) + 8) * PST + (lane & 3)]);
            a4[2] = __float_as_uint(pp[(lane >> 2) * PST + (lane & 3) + 4]);
            a4[3] = __float_as_uint(pp[((lane >> 2) + 8) * PST + (lane & 3) + 4]);
#pragma unroll
            for (int ni = 0; ni < 8; ni++) {
                const float* vp = Vc + (ks * 8 + (lane & 3)) * VST + ni * 8 + (lane >> 2);
                uint32_t b2[2] = { __float_as_uint(vp[0]),
                                   __float_as_uint(vp[4 * VST]) };
                mma_tf32(o[ni], a4, b2);
            }
        }

        if (kt + 1 < NKT) stsT(Vs + (cur ^ 1) * 128 * VST, VST);
        __syncthreads();
    }

    // ---- epilogue: O / l -> out[b][n][h*HD + d] ----
    const float inv0 = 1.f / l0;
    const float inv1 = 1.f / l1;
    const int n0 = q0 + w * 16 + (lane >> 2);
    float* op = out + ((size_t)b * N_ + n0) * HID_ + h * HD_ + 2 * (lane & 3);
#pragma unroll
    for (int ni = 0; ni < 8; ni++) {
        *reinterpret_cast<float2*>(op + ni * 8) =
            make_float2(o[ni][0] * inv0, o[ni][1] * inv0);
        *reinterpret_cast<float2*>(op + (size_t)8 * HID_ + ni * 8) =
            make_float2(o[ni][2] * inv1, o[ni][3] * inv1);
    }
}

// ===========================================================================
extern "C" void kernel_launch(void* const* d_in, const int* in_sizes, int n_in,
                              void* d_out, int out_size) {
    const float* X    = (const float*)d_in[0];
    const float* mask = (const float*)d_in[1];
    const float* Wq   = (const float*)d_in[2];
    const float* bq   = (const float*)d_in[3];
    const float* Wk   = (const float*)d_in[4];
    const float* bk   = (const float*)d_in[5];
    const float* Wv   = (const float*)d_in[6];
    const float* bv   = (const float*)d_in[7];
    float* out = (float*)d_out;

    cudaFuncSetAttribute(qkv_kernel,
                         cudaFuncAttributeMaxDynamicSharedMemorySize, QKV_SMEM);
    cudaFuncSetAttribute(attn_kernel,
                         cudaFuncAttributeMaxDynamicSharedMemorySize, ATTN_SMEM);

    // QKV: M=4096 -> 32 blocks, O=1024 -> 8 blocks, z selects Q/K/V
    qkv_kernel<<<dim3(32, 8, 3), 256, QKV_SMEM>>>(X, Wq, bq, Wk, bk, Wv, bv);
    // Attention: (q-tile, head, batch)
    attn_kernel<<<dim3(N_ / 128, NH_, B_), 256, ATTN_SMEM>>>(mask, out);
}

// round 13
// speedup vs baseline: 1.0010x; 1.0004x over previous
#include <cuda_runtime.h>
#include <cstdint>

// ---------------------------------------------------------------------------
// RobertaSelfAttention  B=2, N=2048, HID=1024, NH=16, HD=64
// Plan: tf32 mma.sync (m16n8k8) everywhere, fp32 accumulate.
//   K1: fused QKV projection (X @ W^T + b) -> scratch [b,h,n,d]
//   K2: flash attention per (b,h) with online softmax
// All tf32 operands pass through cvt.rna (round-to-nearest) to avoid the
// biased truncation error of raw f32 bit patterns.
// ---------------------------------------------------------------------------

#define DEVFN __device__ __forceinline__

constexpr int B_  = 2;
constexpr int N_  = 2048;
constexpr int HID_ = 1024;
constexpr int NH_ = 16;
constexpr int HD_ = 64;

// Scratch (static device globals: allocation-free)
__device__ float g_Q[B_ * NH_ * N_ * HD_];
__device__ float g_K[B_ * NH_ * N_ * HD_];
__device__ float g_V[B_ * NH_ * N_ * HD_];

DEVFN uint32_t f2tf(float x) {
    uint32_t u;
    asm("cvt.rna.tf32.f32 %0, %1;" : "=r"(u) : "f"(x));
    return u;
}
DEVFN float f2tff(float x) { return __uint_as_float(f2tf(x)); }

DEVFN void mma_tf32(float* d, const uint32_t* a, const uint32_t* b) {
    asm("mma.sync.aligned.m16n8k8.row.col.f32.tf32.tf32.f32 "
        "{%0,%1,%2,%3}, {%4,%5,%6,%7}, {%8,%9}, {%0,%1,%2,%3};"
        : "+f"(d[0]), "+f"(d[1]), "+f"(d[2]), "+f"(d[3])
        : "r"(a[0]), "r"(a[1]), "r"(a[2]), "r"(a[3]),
          "r"(b[0]), "r"(b[1]));
}

// ===========================================================================
// Kernel 1: QKV projection GEMM.  out[m,o] = sum_k X[m,k] * W[o,k] + b[o]
// BM=128 BN=128 BK=32, 256 threads (8 warps, 4x2), warp tile 32x64.
// Double-buffered smem, register-staged global loads, tf32 rounding at STS.
// blockIdx.z in {0,1,2} selects (Wq,bq,g_Q) / (Wk,bk,g_K) / (Wv,bv,g_V).
// Writes scratch in [b][h][n][d] layout.
// ===========================================================================
constexpr int BM = 128, BN = 128, BK = 32;
constexpr int AST = BK + 4;  // 36: stride ≡ 4 (mod 32) -> conflict-free frags
constexpr int QKV_SMEM = (2 * BM * AST + 2 * BN * AST) * 4;  // 73728 B

__global__ void __launch_bounds__(256, 1)
qkv_kernel(const float* __restrict__ X,
           const float* __restrict__ Wq, const float* __restrict__ bq,
           const float* __restrict__ Wk, const float* __restrict__ bk,
           const float* __restrict__ Wv, const float* __restrict__ bv) {
    extern __shared__ float sm[];
    float* As = sm;                  // [2][BM][AST]
    float* Bs = sm + 2 * BM * AST;   // [2][BN][AST]

    const int z = blockIdx.z;
    const float* W    = (z == 0) ? Wq : (z == 1) ? Wk : Wv;
    const float* bias = (z == 0) ? bq : (z == 1) ? bk : bv;
    float* dst        = (z == 0) ? g_Q : (z == 1) ? g_K : g_V;

    const int m0 = blockIdx.x * BM;
    const int o0 = blockIdx.y * BN;
    const int tid = threadIdx.x;
    const int lane = tid & 31;
    const int w = tid >> 5;
    const int wm = w & 3;   // 4 warps along M
    const int wn = w >> 2;  // 2 warps along N

    // staging: 128 rows x 8 float4 per row; thread covers rows srow+32i
    const int srow = tid >> 3;
    const int scol = (tid & 7) * 4;
    const float* Xp = X + (size_t)(m0 + srow) * HID_ + scol;
    const float* Wp = W + (size_t)(o0 + srow) * HID_ + scol;

    float4 ar[4], br[4];
    auto ldg = [&](int kt) {
#pragma unroll
        for (int i = 0; i < 4; i++) {
            ar[i] = *reinterpret_cast<const float4*>(Xp + kt * BK + (size_t)i * 32 * HID_);
            br[i] = *reinterpret_cast<const float4*>(Wp + kt * BK + (size_t)i * 32 * HID_);
        }
    };
    auto sts = [&](int buf) {
#pragma unroll
        for (int i = 0; i < 4; i++) {
            float* pa = As + buf * BM * AST + (srow + i * 32) * AST + scol;
            pa[0] = f2tff(ar[i].x); pa[1] = f2tff(ar[i].y);
            pa[2] = f2tff(ar[i].z); pa[3] = f2tff(ar[i].w);
            float* pb = Bs + buf * BN * AST + (srow + i * 32) * AST + scol;
            pb[0] = f2tff(br[i].x); pb[1] = f2tff(br[i].y);
            pb[2] = f2tff(br[i].z); pb[3] = f2tff(br[i].w);
        }
    };

    float acc[2][8][4];
#pragma unroll
    for (int mi = 0; mi < 2; mi++)
#pragma unroll
        for (int ni = 0; ni < 8; ni++)
#pragma unroll
            for (int r = 0; r < 4; r++) acc[mi][ni][r] = 0.f;

    ldg(0);
    sts(0);
    __syncthreads();

    const int KT = HID_ / BK;  // 32
    for (int kt = 0; kt < KT; kt++) {
        const int cur = kt & 1;
        if (kt + 1 < KT) ldg(kt + 1);

        const float* Ab = As + cur * BM * AST + (wm * 32) * AST;
        const float* Bb = Bs + cur * BN * AST + (wn * 64) * AST;
#pragma unroll
        for (int ks = 0; ks < 4; ks++) {
            uint32_t a[2][4];
#pragma unroll
            for (int mi = 0; mi < 2; mi++) {
                const float* ap = Ab + mi * 16 * AST + ks * 8;
                a[mi][0] = __float_as_uint(ap[(lane >> 2) * AST + (lane & 3)]);
                a[mi][1] = __float_as_uint(ap[((lane >> 2) + 8) * AST + (lane & 3)]);
                a[mi][2] = __float_as_uint(ap[(lane >> 2) * AST + (lane & 3) + 4]);
                a[mi][3] = __float_as_uint(ap[((lane >> 2) + 8) * AST + (lane & 3) + 4]);
            }
#pragma unroll
            for (int ni = 0; ni < 8; ni++) {
                const float* bp = Bb + ni * 8 * AST + ks * 8;
                uint32_t b2[2];
                b2[0] = __float_as_uint(bp[(lane >> 2) * AST + (lane & 3)]);
                b2[1] = __float_as_uint(bp[(lane >> 2) * AST + (lane & 3) + 4]);
                mma_tf32(acc[0][ni], a[0], b2);
                mma_tf32(acc[1][ni], a[1], b2);
            }
        }
        if (kt + 1 < KT) sts((kt + 1) & 1);
        __syncthreads();
    }

    // Epilogue: add bias, scatter to [b][h][n][d]
#pragma unroll
    for (int mi = 0; mi < 2; mi++) {
        const int row = m0 + wm * 32 + mi * 16 + (lane >> 2);
        const int bb = row >> 11;       // / N_
        const int nn = row & (N_ - 1);
#pragma unroll
        for (int ni = 0; ni < 8; ni++) {
            const int col = o0 + wn * 64 + ni * 8 + 2 * (lane & 3);
            const int hh = col >> 6;
            const int dd = col & 63;
            const float b0v = bias[col];
            const float b1v = bias[col + 1];
            float* p0 = dst + (((size_t)(bb * NH_ + hh) * N_ + nn) * HD_ + dd);
            float* p1 = dst + (((size_t)(bb * NH_ + hh) * N_ + nn + 8) * HD_ + dd);
            float2 v0 = make_float2(acc[mi][ni][0] + b0v, acc[mi][ni][1] + b1v);
            float2 v1 = make_float2(acc[mi][ni][2] + b0v, acc[mi][ni][3] + b1v);
            *reinterpret_cast<float2*>(p0) = v0;
            *reinterpret_cast<float2*>(p1) = v1;
        }
    }
}

// ===========================================================================
// Kernel 2: flash attention.  grid (N/128, NH, B), 256 threads (8 warps).
// Each warp owns 16 query rows. Q fragments live in registers (scale folded).
// K/V tiles (128x64) double-buffered in smem with LDG->cvt->STS staging.
// P staged through smem (tf32) for the PV mma.
// Smem strides: Ks 68 (≡4 mod 32), Vs 72 (≡8), Ps 132 (≡4) -> fragment LDS
// patterns are bank-conflict-free.
// ===========================================================================
constexpr int KST = 68, VST = 72, PST = 132;
constexpr int ATTN_SMEM =
    (2 * 128 * KST + 2 * 128 * VST + 128 * PST + N_) * 4;  // 219136 B

__global__ void __launch_bounds__(256, 1)
attn_kernel(const float* __restrict__ mask, float* __restrict__ out) {
    extern __shared__ float sm[];
    float* Ks = sm;                      // [2][128][KST]
    float* Vs = Ks + 2 * 128 * KST;      // [2][128][VST]
    float* Ps = Vs + 2 * 128 * VST;      // [128][PST]
    float* Ms = Ps + 128 * PST;          // [N_]

    const int b = blockIdx.z;
    const int h = blockIdx.y;
    const int q0 = blockIdx.x * 128;
    const int tid = threadIdx.x;
    const int lane = tid & 31;
    const int w = tid >> 5;

    const size_t hb = (size_t)(b * NH_ + h) * N_ * HD_;
    const float* Qb = g_Q + hb + (size_t)q0 * HD_;
    const float* Kb = g_K + hb;
    const float* Vb = g_V + hb;

    // whole-sequence mask for this batch into smem (8 KB)
    {
        const float4* mp = reinterpret_cast<const float4*>(mask + (size_t)b * N_);
        float4* ms = reinterpret_cast<float4*>(Ms);
#pragma unroll
        for (int i = 0; i < 2; i++) ms[tid + 256 * i] = mp[tid + 256 * i];
    }

    // Q fragments in registers (scale 1/8 folded in, tf32-rounded)
    uint32_t qf[8][4];
    {
        const float* qp = Qb + (size_t)(w * 16 + (lane >> 2)) * HD_;
#pragma unroll
        for (int ks = 0; ks < 8; ks++) {
            qf[ks][0] = f2tf(qp[ks * 8 + (lane & 3)] * 0.125f);
            qf[ks][1] = f2tf(qp[8 * HD_ + ks * 8 + (lane & 3)] * 0.125f);
            qf[ks][2] = f2tf(qp[ks * 8 + (lane & 3) + 4] * 0.125f);
            qf[ks][3] = f2tf(qp[8 * HD_ + ks * 8 + (lane & 3) + 4] * 0.125f);
        }
    }

    // tile staging: 128 rows x 16 float4 per row
    const int srow = tid >> 4;
    const int scol = (tid & 15) * 4;
    float4 stg[8];
    auto ldgT = [&](const float* base, int kt) {
        const float* p = base + (size_t)(kt * 128 + srow) * HD_ + scol;
#pragma unroll
        for (int i = 0; i < 8; i++)
            stg[i] = *reinterpret_cast<const float4*>(p + (size_t)i * 16 * HD_);
    };
    auto stsT = [&](float* dstS, int stride) {
#pragma unroll
        for (int i = 0; i < 8; i++) {
            float* p = dstS + (srow + i * 16) * stride + scol;
            p[0] = f2tff(stg[i].x); p[1] = f2tff(stg[i].y);
            p[2] = f2tff(stg[i].z); p[3] = f2tff(stg[i].w);
        }
    };

    ldgT(Kb, 0); stsT(Ks, KST);
    ldgT(Vb, 0); stsT(Vs, VST);
    __syncthreads();

    float o[8][4];
#pragma unroll
    for (int ni = 0; ni < 8; ni++)
#pragma unroll
        for (int r = 0; r < 4; r++) o[ni][r] = 0.f;
    float m0r = -INFINITY, m1r = -INFINITY, l0 = 0.f, l1 = 0.f;

    const int NKT = N_ / 128;  // 16
    for (int kt = 0; kt < NKT; kt++) {
        const int cur = kt & 1;
        const float* Kc = Ks + cur * 128 * KST;
        const float* Vc = Vs + cur * 128 * VST;

        if (kt + 1 < NKT) ldgT(Kb, kt + 1);  // prefetch K(kt+1) into regs

        // ---- S = Q K^T (pre-scaled) ----
        float s[16][4];
#pragma unroll
        for (int ni = 0; ni < 16; ni++)
#pragma unroll
            for (int r = 0; r < 4; r++) s[ni][r] = 0.f;

#pragma unroll
        for (int ks = 0; ks < 8; ks++) {
#pragma unroll
            for (int ni = 0; ni < 16; ni++) {
                const float* bp = Kc + (ni * 8 + (lane >> 2)) * KST + ks * 8 + (lane & 3);
                uint32_t b2[2] = { __float_as_uint(bp[0]), __float_as_uint(bp[4]) };
                mma_tf32(s[ni], qf[ks], b2);
            }
        }

        // ---- online softmax ----
        float mx0 = -INFINITY, mx1 = -INFINITY;
#pragma unroll
        for (int ni = 0; ni < 16; ni++) {
            const float2 mk = *reinterpret_cast<const float2*>(
                Ms + kt * 128 + ni * 8 + 2 * (lane & 3));
            s[ni][0] += mk.x; s[ni][1] += mk.y;
            s[ni][2] += mk.x; s[ni][3] += mk.y;
            mx0 = fmaxf(mx0, fmaxf(s[ni][0], s[ni][1]));
            mx1 = fmaxf(mx1, fmaxf(s[ni][2], s[ni][3]));
        }
        mx0 = fmaxf(mx0, __shfl_xor_sync(0xffffffffu, mx0, 1));
        mx0 = fmaxf(mx0, __shfl_xor_sync(0xffffffffu, mx0, 2));
        mx1 = fmaxf(mx1, __shfl_xor_sync(0xffffffffu, mx1, 1));
        mx1 = fmaxf(mx1, __shfl_xor_sync(0xffffffffu, mx1, 2));

        const float mn0 = fmaxf(m0r, mx0);
        const float mn1 = fmaxf(m1r, mx1);
        const float a0 = __expf(m0r - mn0);
        const float a1 = __expf(m1r - mn1);
        m0r = mn0; m1r = mn1;

        float rs0 = 0.f, rs1 = 0.f;
#pragma unroll
        for (int ni = 0; ni < 16; ni++) {
            s[ni][0] = __expf(s[ni][0] - mn0);
            s[ni][1] = __expf(s[ni][1] - mn0);
            s[ni][2] = __expf(s[ni][2] - mn1);
            s[ni][3] = __expf(s[ni][3] - mn1);
            rs0 += s[ni][0] + s[ni][1];
            rs1 += s[ni][2] + s[ni][3];
        }
        rs0 += __shfl_xor_sync(0xffffffffu, rs0, 1);
        rs0 += __shfl_xor_sync(0xffffffffu, rs0, 2);
        rs1 += __shfl_xor_sync(0xffffffffu, rs1, 1);
        rs1 += __shfl_xor_sync(0xffffffffu, rs1, 2);
        l0 = l0 * a0 + rs0;
        l1 = l1 * a1 + rs1;

        // ---- write P (tf32) to smem ----
        {
            float* pr = Ps + (w * 16 + (lane >> 2)) * PST + 2 * (lane & 3);
#pragma unroll
            for (int ni = 0; ni < 16; ni++) {
                *reinterpret_cast<float2*>(pr + ni * 8) =
                    make_float2(f2tff(s[ni][0]), f2tff(s[ni][1]));
                *reinterpret_cast<float2*>(pr + 8 * PST + ni * 8) =
                    make_float2(f2tff(s[ni][2]), f2tff(s[ni][3]));
            }
        }
        __syncthreads();  // Ps visible; alt K buffer fully consumed (kt-1)

        if (kt + 1 < NKT) {
            stsT(Ks + (cur ^ 1) * 128 * KST, KST);  // commit staged K
            ldgT(Vb, kt + 1);                       // prefetch V(kt+1)
        }

        // ---- O = O*alpha + P V ----
#pragma unroll
        for (int ni = 0; ni < 8; ni++) {
            o[ni][0] *= a0; o[ni][1] *= a0;
            o[ni][2] *= a1; o[ni][3] *= a1;
        }
#pragma unroll
        for (int ks = 0; ks < 16; ks++) {
            const float* pp = Ps + (w * 16) * PST + ks * 8;
            uint32_t a4[4];
            a4[0] = __float_as_uint(pp[(lane >> 2) * PST + (lane & 3)]);
            a4[1] = __float_as_uint(pp[((lane >> 2) + 8) * PST + (lane & 3)]);
            a4[2] = __float_as_uint(pp[(lane >> 2) * PST + (lane & 3) + 4]);
            a4[3] = __float_as_uint(pp[((lane >> 2) + 8) * PST + (lane & 3) + 4]);
#pragma unroll
            for (int ni = 0; ni < 8; ni++) {
                const float* vp = Vc + (ks * 8 + (lane & 3)) * VST + ni * 8 + (lane >> 2);
                uint32_t b2[2] = { __float_as_uint(vp[0]),
                                   __float_as_uint(vp[4 * VST]) };
                mma_tf32(o[ni], a4, b2);
            }
        }

        if (kt + 1 < NKT) stsT(Vs + (cur ^ 1) * 128 * VST, VST);
        __syncthreads();
    }

    // ---- epilogue: O / l -> out[b][n][h*HD + d] ----
    const float inv0 = 1.f / l0;
    const float inv1 = 1.f / l1;
    const int n0 = q0 + w * 16 + (lane >> 2);
    float* op = out + ((size_t)b * N_ + n0) * HID_ + h * HD_ + 2 * (lane & 3);
#pragma unroll
    for (int ni = 0; ni < 8; ni++) {
        *reinterpret_cast<float2*>(op + ni * 8) =
            make_float2(o[ni][0] * inv0, o[ni][1] * inv0);
        *reinterpret_cast<float2*>(op + (size_t)8 * HID_ + ni * 8) =
            make_float2(o[ni][2] * inv1, o[ni][3] * inv1);
    }
}

// ===========================================================================
extern "C" void kernel_launch(void* const* d_in, const int* in_sizes, int n_in,
                              void* d_out, int out_size) {
    const float* X    = (const float*)d_in[0];
    const float* mask = (const float*)d_in[1];
    const float* Wq   = (const float*)d_in[2];
    const float* bq   = (const float*)d_in[3];
    const float* Wk   = (const float*)d_in[4];
    const float* bk   = (const float*)d_in[5];
    const float* Wv   = (const float*)d_in[6];
    const float* bv   = (const float*)d_in[7];
    float* out = (float*)d_out;

    cudaFuncSetAttribute(qkv_kernel,
                         cudaFuncAttributeMaxDynamicSharedMemorySize, QKV_SMEM);
    cudaFuncSetAttribute(attn_kernel,
                         cudaFuncAttributeMaxDynamicSharedMemorySize, ATTN_SMEM);

    // QKV: M=4096 -> 32 blocks, O=1024 -> 8 blocks, z selects Q/K/V
    qkv_kernel<<<dim3(32, 8, 3), 256, QKV_SMEM>>>(X, Wq, bq, Wk, bk, Wv, bv);
    // Attention: (q-tile, head, batch)
    attn_kernel<<<dim3(N_ / 128, NH_, B_), 256, ATTN_SMEM>>>(mask, out);
}

// round 15
// speedup vs baseline: 1.2151x; 1.2139x over previous
#include <cuda_runtime.h>
#include <cstdint>

// ---------------------------------------------------------------------------
// RobertaSelfAttention  B=2, N=2048, HID=1024, NH=16, HD=64
// tf32 mma.sync m16n8k8, fp32 accumulate.
//   K1: fused QKV GEMM -> g_Q [b,h,n,d] (pre-scaled 1/8, tf32-rounded),
//       g_K [b,h,n,d] (tf32-rounded), g_V TRANSPOSED [b,h,d,n] (tf32-rounded)
//   K2: flash attention; cp.async staging (operands pre-rounded), no P smem
//       (k-slot relabel makes S accumulators a valid PV A-fragment),
//       all fragment loads LDS.64 via contiguous-pair slot mapping.
// ---------------------------------------------------------------------------

#define DEVFN __device__ __forceinline__

constexpr int B_   = 2;
constexpr int N_   = 2048;
constexpr int HID_ = 1024;
constexpr int NH_  = 16;
constexpr int HD_  = 64;

__device__ float g_Q[B_ * NH_ * N_ * HD_];   // [b,h,n,d], tf32, *0.125
__device__ float g_K[B_ * NH_ * N_ * HD_];   // [b,h,n,d], tf32
__device__ float g_V[B_ * NH_ * N_ * HD_];   // [b,h,d,n] TRANSPOSED, tf32

DEVFN uint32_t f2tf(float x) {
    uint32_t u;
    asm("cvt.rna.tf32.f32 %0, %1;" : "=r"(u) : "f"(x));
    return u;
}
DEVFN float f2tff(float x) { return __uint_as_float(f2tf(x)); }

DEVFN void mma_tf32(float* d, const uint32_t* a, const uint32_t* b) {
    asm("mma.sync.aligned.m16n8k8.row.col.f32.tf32.tf32.f32 "
        "{%0,%1,%2,%3}, {%4,%5,%6,%7}, {%8,%9}, {%0,%1,%2,%3};"
        : "+f"(d[0]), "+f"(d[1]), "+f"(d[2]), "+f"(d[3])
        : "r"(a[0]), "r"(a[1]), "r"(a[2]), "r"(a[3]),
          "r"(b[0]), "r"(b[1]));
}

DEVFN void cpa16(uint32_t dst, const float* src) {
    asm volatile("cp.async.cg.shared.global [%0], [%1], 16;"
                 :: "r"(dst), "l"(src));
}
#define CP_COMMIT asm volatile("cp.async.commit_group;" ::: "memory")
#define CP_WAIT0  asm volatile("cp.async.wait_group 0;"  ::: "memory")

// ===========================================================================
// Kernel 1: QKV projection.  out[m,o] = sum_k X[m,k]*W[o,k] + b[o]
// BM=128 BN=128 BK=32, 256 thr (8 warps 4x2), warp tile 32x64.
// Fragment pairs loaded as contiguous LDS.64 via k-slot relabeling
// (slot c <-> phys 2c, slot c+4 <-> phys 2c+1; A and B agree -> valid).
// ===========================================================================
constexpr int BM = 128, BN = 128, BK = 32;
constexpr int AST = 40;  // ≡8 (mod 32): LDS.64 frag pattern conflict-free
constexpr int QKV_SMEM = (2 * BM * AST + 2 * BN * AST) * 4;  // 81920 B

__global__ void __launch_bounds__(256, 1)
qkv_kernel(const float* __restrict__ X,
           const float* __restrict__ Wq, const float* __restrict__ bq,
           const float* __restrict__ Wk, const float* __restrict__ bk,
           const float* __restrict__ Wv, const float* __restrict__ bv) {
    extern __shared__ float sm[];
    float* As = sm;                  // [2][BM][AST]
    float* Bs = sm + 2 * BM * AST;   // [2][BN][AST]

    const int z = blockIdx.z;
    const float* W    = (z == 0) ? Wq : (z == 1) ? Wk : Wv;
    const float* bias = (z == 0) ? bq : (z == 1) ? bk : bv;

    const int m0 = blockIdx.x * BM;
    const int o0 = blockIdx.y * BN;
    const int tid = threadIdx.x;
    const int lane = tid & 31;
    const int w = tid >> 5;
    const int wm = w & 3;
    const int wn = w >> 2;

    const int srow = tid >> 3;
    const int scol = (tid & 7) * 4;
    const float* Xp = X + (size_t)(m0 + srow) * HID_ + scol;
    const float* Wp = W + (size_t)(o0 + srow) * HID_ + scol;

    float4 ar[4], br[4];
    auto ldg = [&](int kt) {
#pragma unroll
        for (int i = 0; i < 4; i++) {
            ar[i] = *reinterpret_cast<const float4*>(Xp + kt * BK + (size_t)i * 32 * HID_);
            br[i] = *reinterpret_cast<const float4*>(Wp + kt * BK + (size_t)i * 32 * HID_);
        }
    };
    auto sts = [&](int buf) {
#pragma unroll
        for (int i = 0; i < 4; i++) {
            float* pa = As + buf * BM * AST + (srow + i * 32) * AST + scol;
            pa[0] = f2tff(ar[i].x); pa[1] = f2tff(ar[i].y);
            pa[2] = f2tff(ar[i].z); pa[3] = f2tff(ar[i].w);
            float* pb = Bs + buf * BN * AST + (srow + i * 32) * AST + scol;
            pb[0] = f2tff(br[i].x); pb[1] = f2tff(br[i].y);
            pb[2] = f2tff(br[i].z); pb[3] = f2tff(br[i].w);
        }
    };

    float acc[2][8][4];
#pragma unroll
    for (int mi = 0; mi < 2; mi++)
#pragma unroll
        for (int ni = 0; ni < 8; ni++)
#pragma unroll
            for (int r = 0; r < 4; r++) acc[mi][ni][r] = 0.f;

    ldg(0);
    sts(0);
    __syncthreads();

    const int KT = HID_ / BK;  // 32
    for (int kt = 0; kt < KT; kt++) {
        const int cur = kt & 1;
        if (kt + 1 < KT) ldg(kt + 1);

        const float* Ab = As + cur * BM * AST + (wm * 32) * AST;
        const float* Bb = Bs + cur * BN * AST + (wn * 64) * AST;
#pragma unroll
        for (int ks = 0; ks < 4; ks++) {
            uint32_t a[2][4];
#pragma unroll
            for (int mi = 0; mi < 2; mi++) {
                const float* ap = Ab + (mi * 16 + (lane >> 2)) * AST
                                  + ks * 8 + 2 * (lane & 3);
                const float2 t0 = *reinterpret_cast<const float2*>(ap);
                const float2 t1 = *reinterpret_cast<const float2*>(ap + 8 * AST);
                a[mi][0] = __float_as_uint(t0.x);
                a[mi][2] = __float_as_uint(t0.y);
                a[mi][1] = __float_as_uint(t1.x);
                a[mi][3] = __float_as_uint(t1.y);
            }
#pragma unroll
            for (int ni = 0; ni < 8; ni++) {
                const float2 bb2 = *reinterpret_cast<const float2*>(
                    Bb + (ni * 8 + (lane >> 2)) * AST + ks * 8 + 2 * (lane & 3));
                uint32_t b2[2] = { __float_as_uint(bb2.x), __float_as_uint(bb2.y) };
                mma_tf32(acc[0][ni], a[0], b2);
                mma_tf32(acc[1][ni], a[1], b2);
            }
        }
        if (kt + 1 < KT) sts((kt + 1) & 1);
        __syncthreads();
    }

    // Epilogue: bias, tf32-round; Q pre-scaled; V stored transposed [b,h,d,n]
#pragma unroll
    for (int mi = 0; mi < 2; mi++) {
        const int row = m0 + wm * 32 + mi * 16 + (lane >> 2);
        const int bb = row >> 11;       // / N_
        const int nn = row & (N_ - 1);
#pragma unroll
        for (int ni = 0; ni < 8; ni++) {
            const int col = o0 + wn * 64 + ni * 8 + 2 * (lane & 3);
            const int hh = col >> 6;
            const int dd = col & 63;
            const float b0v = bias[col];
            const float b1v = bias[col + 1];
            float v00 = acc[mi][ni][0] + b0v;
            float v01 = acc[mi][ni][1] + b1v;
            float v10 = acc[mi][ni][2] + b0v;
            float v11 = acc[mi][ni][3] + b1v;
            if (z == 0) { v00 *= 0.125f; v01 *= 0.125f; v10 *= 0.125f; v11 *= 0.125f; }
            v00 = f2tff(v00); v01 = f2tff(v01);
            v10 = f2tff(v10); v11 = f2tff(v11);
            if (z == 2) {
                float* base = g_V + ((size_t)(bb * NH_ + hh) * HD_ + dd) * N_;
                base[nn]          = v00;
                base[N_ + nn]     = v01;
                base[nn + 8]      = v10;
                base[N_ + nn + 8] = v11;
            } else {
                float* dst = (z == 0) ? g_Q : g_K;
                float* p0 = dst + (((size_t)(bb * NH_ + hh) * N_ + nn) * HD_ + dd);
                *reinterpret_cast<float2*>(p0) = make_float2(v00, v01);
                *reinterpret_cast<float2*>(p0 + 8 * HD_) = make_float2(v10, v11);
            }
        }
    }
}

// ===========================================================================
// Kernel 2: flash attention.  grid (N/128, NH, B), 256 threads (8 warps).
// K tile [128 keys][64 d] stride 72; V tile transposed [64 d][128 keys]
// stride 136 (both ≡8 mod 32 -> LDS.64 conflict-free). cp.async staging,
// double-buffered. PV A-fragments come directly from the S accumulators
// (k-slot relabel: slot c <-> key 2c, slot c+4 <-> key 2c+1).
// ===========================================================================
constexpr int KST = 72, VTST = 136;
constexpr int ATTN_SMEM =
    (2 * 128 * KST + 2 * 64 * VTST + N_) * 4;  // 151552 B

__global__ void __launch_bounds__(256, 1)
attn_kernel(const float* __restrict__ mask, float* __restrict__ out) {
    extern __shared__ float sm[];
    float* Ks = sm;                      // [2][128][KST]
    float* Vs = Ks + 2 * 128 * KST;      // [2][64][VTST]
    float* Ms = Vs + 2 * 64 * VTST;      // [N_]

    const int b = blockIdx.z;
    const int h = blockIdx.y;
    const int q0 = blockIdx.x * 128;
    const int tid = threadIdx.x;
    const int lane = tid & 31;
    const int w = tid >> 5;
    const int r = lane >> 2;
    const int c2 = 2 * (lane & 3);

    const size_t hb = (size_t)(b * NH_ + h) * N_ * HD_;
    const float* Qb  = g_Q + hb + (size_t)q0 * HD_;
    const float* Kb  = g_K + hb;
    const float* Vtb = g_V + hb;   // [HD_][N_]

    const uint32_t smKu = (uint32_t)__cvta_generic_to_shared(Ks);
    const uint32_t smVu = (uint32_t)__cvta_generic_to_shared(Vs);

    auto loadK = [&](int kt, int buf) {
        const uint32_t dst0 = smKu + buf * (128 * KST * 4);
        const float* src0 = Kb + (size_t)kt * 128 * HD_;
#pragma unroll
        for (int i = 0; i < 8; i++) {
            const int idx = tid + 256 * i;
            const int row = idx >> 4, c4 = (idx & 15) << 2;
            cpa16(dst0 + (row * KST + c4) * 4, src0 + row * HD_ + c4);
        }
    };
    auto loadV = [&](int kt, int buf) {
        const uint32_t dst0 = smVu + buf * (64 * VTST * 4);
        const float* src0 = Vtb + kt * 128;
#pragma unroll
        for (int i = 0; i < 8; i++) {
            const int idx = tid + 256 * i;
            const int row = idx >> 5, c4 = (idx & 31) << 2;
            cpa16(dst0 + (row * VTST + c4) * 4, src0 + (size_t)row * N_ + c4);
        }
    };

    loadK(0, 0);
    loadV(0, 0);
    CP_COMMIT;

    // mask for this batch -> smem (8 KB)
    {
        const float4* mp = reinterpret_cast<const float4*>(mask + (size_t)b * N_);
        float4* ms = reinterpret_cast<float4*>(Ms);
#pragma unroll
        for (int i = 0; i < 2; i++) ms[tid + 256 * i] = mp[tid + 256 * i];
    }

    // Q fragments (already tf32-rounded and pre-scaled in g_Q)
    uint32_t qf[8][4];
    {
        const float* qp = Qb + (size_t)(w * 16 + r) * HD_;
#pragma unroll
        for (int ks = 0; ks < 8; ks++) {
            const float2 t0 = *reinterpret_cast<const float2*>(qp + ks * 8 + c2);
            const float2 t1 = *reinterpret_cast<const float2*>(qp + 8 * HD_ + ks * 8 + c2);
            qf[ks][0] = __float_as_uint(t0.x);
            qf[ks][2] = __float_as_uint(t0.y);
            qf[ks][1] = __float_as_uint(t1.x);
            qf[ks][3] = __float_as_uint(t1.y);
        }
    }

    CP_WAIT0;
    __syncthreads();

    float o[8][4];
#pragma unroll
    for (int ni = 0; ni < 8; ni++)
#pragma unroll
        for (int q = 0; q < 4; q++) o[ni][q] = 0.f;
    float m0r = -INFINITY, m1r = -INFINITY, l0 = 0.f, l1 = 0.f;

    const int NKT = N_ / 128;  // 16
    for (int kt = 0; kt < NKT; kt++) {
        const int cur = kt & 1;
        const float* Kc = Ks + cur * 128 * KST;
        const float* Vc = Vs + cur * 64 * VTST;

        if (kt + 1 < NKT) {
            loadK(kt + 1, cur ^ 1);
            loadV(kt + 1, cur ^ 1);
            CP_COMMIT;
        }

        // ---- S = Q K^T (pre-scaled) ----
        float s[16][4];
#pragma unroll
        for (int ni = 0; ni < 16; ni++)
#pragma unroll
            for (int q = 0; q < 4; q++) s[ni][q] = 0.f;

#pragma unroll
        for (int ks = 0; ks < 8; ks++) {
#pragma unroll
            for (int ni = 0; ni < 16; ni++) {
                const float2 kb2 = *reinterpret_cast<const float2*>(
                    Kc + (ni * 8 + r) * KST + ks * 8 + c2);
                uint32_t b2[2] = { __float_as_uint(kb2.x), __float_as_uint(kb2.y) };
                mma_tf32(s[ni], qf[ks], b2);
            }
        }

        // ---- online softmax ----
        float mx0 = -INFINITY, mx1 = -INFINITY;
#pragma unroll
        for (int ni = 0; ni < 16; ni++) {
            const float2 mk = *reinterpret_cast<const float2*>(Ms + kt * 128 + ni * 8 + c2);
            s[ni][0] += mk.x; s[ni][1] += mk.y;
            s[ni][2] += mk.x; s[ni][3] += mk.y;
            mx0 = fmaxf(mx0, fmaxf(s[ni][0], s[ni][1]));
            mx1 = fmaxf(mx1, fmaxf(s[ni][2], s[ni][3]));
        }
        mx0 = fmaxf(mx0, __shfl_xor_sync(0xffffffffu, mx0, 1));
        mx0 = fmaxf(mx0, __shfl_xor_sync(0xffffffffu, mx0, 2));
        mx1 = fmaxf(mx1, __shfl_xor_sync(0xffffffffu, mx1, 1));
        mx1 = fmaxf(mx1, __shfl_xor_sync(0xffffffffu, mx1, 2));

        const float mn0 = fmaxf(m0r, mx0);
        const float mn1 = fmaxf(m1r, mx1);
        const float a0 = __expf(m0r - mn0);
        const float a1 = __expf(m1r - mn1);
        m0r = mn0; m1r = mn1;

        float rs0 = 0.f, rs1 = 0.f;
#pragma unroll
        for (int ni = 0; ni < 16; ni++) {
            s[ni][0] = __expf(s[ni][0] - mn0);
            s[ni][1] = __expf(s[ni][1] - mn0);
            s[ni][2] = __expf(s[ni][2] - mn1);
            s[ni][3] = __expf(s[ni][3] - mn1);
            rs0 += s[ni][0] + s[ni][1];
            rs1 += s[ni][2] + s[ni][3];
        }
        rs0 += __shfl_xor_sync(0xffffffffu, rs0, 1);
        rs0 += __shfl_xor_sync(0xffffffffu, rs0, 2);
        rs1 += __shfl_xor_sync(0xffffffffu, rs1, 1);
        rs1 += __shfl_xor_sync(0xffffffffu, rs1, 2);
        l0 = l0 * a0 + rs0;
        l1 = l1 * a1 + rs1;

        // ---- O = O*alpha + P V  (A-fragment = relabeled S accumulators) ----
#pragma unroll
        for (int ni = 0; ni < 8; ni++) {
            o[ni][0] *= a0; o[ni][1] *= a0;
            o[ni][2] *= a1; o[ni][3] *= a1;
        }
#pragma unroll
        for (int kg = 0; kg < 16; kg++) {
            // slot c <-> key 2c, slot c+4 <-> key 2c+1:
            // a0=P(r,2c)=s0, a1=P(r+8,2c)=s2, a2=P(r,2c+1)=s1, a3=s3
            uint32_t a4[4];
            a4[0] = f2tf(s[kg][0]);
            a4[1] = f2tf(s[kg][2]);
            a4[2] = f2tf(s[kg][1]);
            a4[3] = f2tf(s[kg][3]);
#pragma unroll
            for (int ni = 0; ni < 8; ni++) {
                const float2 vb2 = *reinterpret_cast<const float2*>(
                    Vc + (ni * 8 + r) * VTST + kg * 8 + c2);
                uint32_t b2[2] = { __float_as_uint(vb2.x), __float_as_uint(vb2.y) };
                mma_tf32(o[ni], a4, b2);
            }
        }

        if (kt + 1 < NKT) CP_WAIT0;
        __syncthreads();
    }

    // ---- epilogue: O / l -> out[b][n][h*HD + d] ----
    const float inv0 = 1.f / l0;
    const float inv1 = 1.f / l1;
    const int n0 = q0 + w * 16 + r;
    float* op = out + ((size_t)b * N_ + n0) * HID_ + h * HD_ + c2;
#pragma unroll
    for (int ni = 0; ni < 8; ni++) {
        *reinterpret_cast<float2*>(op + ni * 8) =
            make_float2(o[ni][0] * inv0, o[ni][1] * inv0);
        *reinterpret_cast<float2*>(op + (size_t)8 * HID_ + ni * 8) =
            make_float2(o[ni][2] * inv1, o[ni][3] * inv1);
    }
}

// ===========================================================================
extern "C" void kernel_launch(void* const* d_in, const int* in_sizes, int n_in,
                              void* d_out, int out_size) {
    const float* X    = (const float*)d_in[0];
    const float* mask = (const float*)d_in[1];
    const float* Wq   = (const float*)d_in[2];
    const float* bq   = (const float*)d_in[3];
    const float* Wk   = (const float*)d_in[4];
    const float* bk   = (const float*)d_in[5];
    const float* Wv   = (const float*)d_in[6];
    const float* bv   = (const float*)d_in[7];
    float* out = (float*)d_out;

    cudaFuncSetAttribute(qkv_kernel,
                         cudaFuncAttributeMaxDynamicSharedMemorySize, QKV_SMEM);
    cudaFuncSetAttribute(attn_kernel,
                         cudaFuncAttributeMaxDynamicSharedMemorySize, ATTN_SMEM);

    qkv_kernel<<<dim3(32, 8, 3), 256, QKV_SMEM>>>(X, Wq, bq, Wk, bk, Wv, bv);
    attn_kernel<<<dim3(N_ / 128, NH_, B_), 256, ATTN_SMEM>>>(mask, out);
}